// round 2
// baseline (speedup 1.0000x reference)
#include <cuda_runtime.h>
#include <math.h>
#include <stdint.h>

// Problem constants
#define T_STEPS 1024
#define B_SZ    64
#define IN_SZ   512
#define HID_SZ  512
#define NCOL    2048          // 4 gates * HID
#define M_ROWS  (T_STEPS * B_SZ)   // 65536

// ---------------- device scratch (static; no runtime allocation) ------------
__device__ float g_WX[IN_SZ * NCOL];                 // [k][g*512+n]  4 MB
__device__ float g_WH[HID_SZ * NCOL];                // [k][g*512+n]  4 MB
__device__ float g_XG[(size_t)M_ROWS * NCOL];        // 512 MB: X@Wx + bias
__device__ float g_HT[2][HID_SZ * B_SZ];             // transposed H, double buffer
__device__ unsigned int g_bar_count = 0;
__device__ volatile unsigned int g_bar_sense = 0;

// ---------------- kernel 1: threshold-mask + transpose weights --------------
__global__ void mask_weights(const float* __restrict__ Wx,
                             const float* __restrict__ Wh,
                             const float* __restrict__ thr) {
    int idx = blockIdx.x * blockDim.x + threadIdx.x;   // over 4*512*512
    if (idx >= 4 * HID_SZ * IN_SZ) return;
    int g = idx / (HID_SZ * IN_SZ);
    int rem = idx % (HID_SZ * IN_SZ);
    int n = rem / IN_SZ;     // output neuron
    int i = rem % IN_SZ;     // contraction index
    float wx = Wx[idx];
    float tx = thr[n * 8 + g];
    g_WX[(size_t)i * NCOL + g * HID_SZ + n] = (fabsf(wx) >= tx) ? wx : 0.0f;
    float wh = Wh[idx];
    float th = thr[n * 8 + 4 + g];
    g_WH[(size_t)i * NCOL + g * HID_SZ + n] = (fabsf(wh) >= th) ? wh : 0.0f;
}

// ---------------- kernel 2: XG = X @ WX + bias  (65536 x 2048 x 512) --------
// classic 128x128x16 fp32 tile, 256 threads, 8x8 per thread
#define BM 128
#define BN 128
#define BK 16
__global__ void __launch_bounds__(256, 2)
gemm_xw(const float* __restrict__ X, const float* __restrict__ bias) {
    __shared__ float As[BK][BM];   // A stored transposed: As[k][m]
    __shared__ float Bs[BK][BN];
    const int tid = threadIdx.x;
    const int bm = blockIdx.y * BM;
    const int bn = blockIdx.x * BN;
    const int tx = tid % 16;
    const int ty = tid / 16;

    float acc[8][8];
#pragma unroll
    for (int i = 0; i < 8; i++)
#pragma unroll
        for (int j = 0; j < 8; j++) acc[i][j] = 0.0f;

    const int a_row  = tid / 4;          // 0..63
    const int a_col4 = (tid % 4) * 4;    // 0,4,8,12
    const int b_row  = tid / 32;         // 0..7
    const int b_col  = (tid % 32) * 4;

    for (int k0 = 0; k0 < IN_SZ; k0 += BK) {
#pragma unroll
        for (int r = 0; r < 2; r++) {
            int m = a_row + r * 64;
            float4 v = *(const float4*)&X[(size_t)(bm + m) * IN_SZ + k0 + a_col4];
            As[a_col4 + 0][m] = v.x;
            As[a_col4 + 1][m] = v.y;
            As[a_col4 + 2][m] = v.z;
            As[a_col4 + 3][m] = v.w;
        }
#pragma unroll
        for (int r = 0; r < 2; r++) {
            int kk = b_row + r * 8;
            *(float4*)&Bs[kk][b_col] =
                *(const float4*)&g_WX[(size_t)(k0 + kk) * NCOL + bn + b_col];
        }
        __syncthreads();
#pragma unroll
        for (int k = 0; k < BK; k++) {
            float ra[8], rb[8];
            *(float4*)&ra[0] = *(const float4*)&As[k][ty * 8];
            *(float4*)&ra[4] = *(const float4*)&As[k][ty * 8 + 4];
            *(float4*)&rb[0] = *(const float4*)&Bs[k][tx * 8];
            *(float4*)&rb[4] = *(const float4*)&Bs[k][tx * 8 + 4];
#pragma unroll
            for (int i = 0; i < 8; i++)
#pragma unroll
                for (int j = 0; j < 8; j++) acc[i][j] += ra[i] * rb[j];
        }
        __syncthreads();
    }
    // epilogue: += bias, store
#pragma unroll
    for (int i = 0; i < 8; i++) {
        size_t m = (size_t)(bm + ty * 8 + i);
#pragma unroll
        for (int j = 0; j < 8; j += 4) {
            int n = bn + tx * 8 + j;
            float4 v;
            v.x = acc[i][j + 0] + bias[n + 0];
            v.y = acc[i][j + 1] + bias[n + 1];
            v.z = acc[i][j + 2] + bias[n + 2];
            v.w = acc[i][j + 3] + bias[n + 3];
            *(float4*)&g_XG[m * NCOL + n] = v;
        }
    }
}

// ---------------- grid barrier (sense-reversing, 128 co-resident CTAs) ------
__device__ __forceinline__ void grid_barrier(unsigned int s) {
    __threadfence();            // publish this thread's writes
    __syncthreads();
    if (threadIdx.x == 0) {
        unsigned int v = atomicAdd(&g_bar_count, 1u);
        if (v == gridDim.x - 1) {
            g_bar_count = 0u;
            __threadfence();
            g_bar_sense = s;
        } else {
            while (g_bar_sense != s) { }
            __threadfence();
        }
    }
    __syncthreads();
}

// ---------------- kernel 3: persistent recurrent LSTM -----------------------
// 128 CTAs x 256 threads. CTA c owns h-columns [c*4, c*4+4) for all 4 gates.
// Wh slice (512x16 = 32KB) resident in SMEM for all steps. C in registers.
__global__ void __launch_bounds__(256, 1)
lstm_recurrent(const float* __restrict__ h0, const float* __restrict__ c0,
               float* __restrict__ out) {
    extern __shared__ float smem[];
    float* Ws = smem;            // [512][16]  = 8192 floats
    float* Hs = smem + 8192;     // [128][64]  = 8192 floats (one K chunk, transposed)
    float* Gs = smem + 16384;    // [64][16]   = 1024 floats

    const int tid = threadIdx.x;
    const int cta = blockIdx.x;          // 0..127
    const int hc0 = cta * 4;

    // Load this CTA's Wh slice: col = g*4+j  <->  WH col n = g*512 + hc0 + j
#pragma unroll 4
    for (int r = 0; r < 32; r++) {
        int idx = r * 256 + tid;         // 0..8191
        int k = idx / 16;
        int col = idx % 16;
        int g = col >> 2, j = col & 3;
        Ws[idx] = g_WH[(size_t)k * NCOL + g * HID_SZ + hc0 + j];
    }

    // GEMM mapping: thread computes rows [rgrp*4, rgrp*4+4) x 1 gate-column
    const int col  = tid % 16;
    const int rgrp = tid / 16;
    // pointwise mapping: thread owns (batch pb, local hidden col phc)
    const int pb  = tid / 4;
    const int phc = tid % 4;

    float creg = c0[pb * HID_SZ + hc0 + phc];

    // init transposed H buffer 0 (this CTA's 4 columns, all batches)
    for (int i = tid; i < 4 * B_SZ; i += 256) {
        int j = i / B_SZ, b = i % B_SZ;
        g_HT[0][(hc0 + j) * B_SZ + b] = h0[b * HID_SZ + hc0 + j];
    }
    grid_barrier(1);

    for (int t = 0; t < T_STEPS; t++) {
        const int cur = t & 1;
        // prefetch XG contributions for the pointwise stage (hides DRAM latency)
        const float* xg = &g_XG[(size_t)(t * B_SZ + pb) * NCOL + hc0 + phc];
        float xgi = __ldg(xg + 0);
        float xgf = __ldg(xg + 512);
        float xgo = __ldg(xg + 1024);
        float xgc = __ldg(xg + 1536);

        float acc0 = 0.f, acc1 = 0.f, acc2 = 0.f, acc3 = 0.f;

#pragma unroll
        for (int kc = 0; kc < 4; kc++) {
            __syncthreads();
            // stage 128x64 transposed H chunk: fully coalesced, L2-only loads
            const float4* src = (const float4*)&g_HT[cur][kc * 8192];
            float4* dst = (float4*)Hs;
#pragma unroll
            for (int r = 0; r < 8; r++) dst[r * 256 + tid] = __ldcg(&src[r * 256 + tid]);
            __syncthreads();
#pragma unroll 4
            for (int k = 0; k < 128; k++) {
                float w = Ws[(kc * 128 + k) * 16 + col];
                float4 h4 = *(const float4*)&Hs[k * 64 + rgrp * 4];
                acc0 += h4.x * w;
                acc1 += h4.y * w;
                acc2 += h4.z * w;
                acc3 += h4.w * w;
            }
        }

        __syncthreads();
        Gs[(rgrp * 4 + 0) * 16 + col] = acc0;
        Gs[(rgrp * 4 + 1) * 16 + col] = acc1;
        Gs[(rgrp * 4 + 2) * 16 + col] = acc2;
        Gs[(rgrp * 4 + 3) * 16 + col] = acc3;
        __syncthreads();

        float gi = Gs[pb * 16 + 0  + phc] + xgi;
        float gf = Gs[pb * 16 + 4  + phc] + xgf;
        float go = Gs[pb * 16 + 8  + phc] + xgo;
        float gc = Gs[pb * 16 + 12 + phc] + xgc;

        float I = 1.0f / (1.0f + expf(-gi));
        float F = 1.0f / (1.0f + expf(-gf));
        float O = 1.0f / (1.0f + expf(-go));
        float Ct = tanhf(gc);
        creg = F * creg + I * Ct;
        float h = O * tanhf(creg);

        g_HT[cur ^ 1][(hc0 + phc) * B_SZ + pb] = h;
        out[(size_t)(t * B_SZ + pb) * HID_SZ + hc0 + phc] = h;

        grid_barrier((unsigned)(t + 2));
    }
}

// ---------------- launcher ---------------------------------------------------
extern "C" void kernel_launch(void* const* d_in, const int* in_sizes, int n_in,
                              void* d_out, int out_size) {
    const float* X    = (const float*)d_in[0];   // (T,B,IN)
    const float* Wx   = (const float*)d_in[1];   // (4,HID,IN)
    const float* Wh   = (const float*)d_in[2];   // (4,HID,HID)
    const float* bias = (const float*)d_in[3];   // (4,HID)
    const float* thr  = (const float*)d_in[4];   // (HID,8)
    const float* h0   = (const float*)d_in[5];   // (B,HID)
    const float* c0   = (const float*)d_in[6];   // (B,HID)
    float* out = (float*)d_out;                  // (T,B,HID)

    // 1) masked + transposed weights
    mask_weights<<<(4 * HID_SZ * IN_SZ + 255) / 256, 256>>>(Wx, Wh, thr);

    // 2) input projection for all timesteps (one big GEMM)
    dim3 g2(NCOL / BN, M_ROWS / BM);   // (16, 512)
    gemm_xw<<<g2, 256>>>(X, bias);

    // 3) persistent recurrent kernel
    const int smem_bytes = (8192 + 8192 + 1024) * sizeof(float);  // 69632
    cudaFuncSetAttribute(lstm_recurrent,
                         cudaFuncAttributeMaxDynamicSharedMemorySize, smem_bytes);
    lstm_recurrent<<<128, 256, smem_bytes>>>(h0, c0, out);
}